// round 15
// baseline (speedup 1.0000x reference)
#include <cuda_runtime.h>
#include <cuda_fp16.h>
#include <mma.h>

using namespace nvcuda;

// ---------------------------------------------------------------------------
// GAT (2-layer, PyG-style) on GB300 — R14: fp16 feature rows (11-bit mantissa,
// per-stage ~1.4e-4 — unlike bf16's 1.1e-3 which failed in R12), tf32 gemm1,
// fp32-SIMT gemm2 (tf32 gemm2 measured SLOWER at N=64 in R13 — reverted).
//
// Pipeline:
//   CSR build (6 small kernels): dst-sorted in-edge lists
//   gemm1_tf32 : h1 = x@W1 (wmma tf32); h1 stored FP16; alpha1 from fp32 acc
//   gather1    : warp/node softmax-aggregate (fp16 h1 rows, 256B/edge) ->
//                x2 = elu(num/den + b1) in FP32 (GEMM-input errors don't avg)
//   gemm2_simt : h2 = x2@W2 (fp32 4x4 register tile); h2 stored FP16 + alpha2
//   gather2    : warp/node (fp16 h2 rows, 128B/edge) -> out = num/den + b2
//
// Softmax max-shift dropped (|e| small, exp bounded — exact same math).
// edge_index is int32 (JAX x64 disabled).
// ---------------------------------------------------------------------------

#define NEG_SLOPE 0.2f
#define MAXN 100000
#define MAXE 1600000

__device__ __align__(16) __half g_h1h[MAXN * 128];
__device__ __align__(16) __half g_h2h[MAXN * 64];
__device__ __align__(16) float g_x2 [MAXN * 128];
__device__ __align__(16) float g_as1[MAXN * 4];
__device__ __align__(16) float g_ad1[MAXN * 4];
__device__ __align__(16) float g_as2[MAXN];
__device__ __align__(16) float g_ad2[MAXN];

__device__ int g_deg [MAXN];
__device__ int g_fill[MAXN];
__device__ int g_off [MAXN + 1];
__device__ int g_aux [128];
__device__ int g_csr [MAXE];

__device__ __forceinline__ float lrelu(float e) { return fmaxf(e, NEG_SLOPE * e); }
__device__ __forceinline__ float elu(float v)   { return (v > 0.f) ? v : (expf(v) - 1.f); }

// ---------------------------- CSR build ------------------------------------
__global__ void csr_zero(int N) {
    int i = blockIdx.x * blockDim.x + threadIdx.x;
    if (i < N) { g_deg[i] = 0; g_fill[i] = 0; }
}

__global__ void csr_hist(const int* __restrict__ ei, int E) {
    int e = blockIdx.x * blockDim.x + threadIdx.x;
    if (e < E) atomicAdd(&g_deg[ei[E + e]], 1);
}

__global__ __launch_bounds__(1024) void scan1(int N) {
    __shared__ int sm[1024];
    int t = threadIdx.x;
    int i = blockIdx.x * 1024 + t;
    sm[t] = (i < N) ? g_deg[i] : 0;
    __syncthreads();
    for (int ofs = 1; ofs < 1024; ofs <<= 1) {
        int add = (t >= ofs) ? sm[t - ofs] : 0;
        __syncthreads();
        sm[t] += add;
        __syncthreads();
    }
    if (i < N) g_off[i + 1] = sm[t];
    if (t == 1023) g_aux[blockIdx.x] = sm[1023];
    if (i == 0) g_off[0] = 0;
}

__global__ void scan2(int NB) {
    __shared__ int sm[128];
    int t = threadIdx.x;
    sm[t] = (t < NB) ? g_aux[t] : 0;
    __syncthreads();
    for (int ofs = 1; ofs < 128; ofs <<= 1) {
        int add = (t >= ofs) ? sm[t - ofs] : 0;
        __syncthreads();
        sm[t] += add;
        __syncthreads();
    }
    if (t < NB) g_aux[t] = (t == 0) ? 0 : sm[t - 1];
}

__global__ void scan3(int N) {
    int i = blockIdx.x * blockDim.x + threadIdx.x;
    if (i < N) g_off[i + 1] += g_aux[i >> 10];
}

__global__ void csr_scatter(const int* __restrict__ ei, int E) {
    int e = blockIdx.x * blockDim.x + threadIdx.x;
    if (e >= E) return;
    int d = ei[E + e];
    int pos = g_off[d] + atomicAdd(&g_fill[d], 1);
    g_csr[pos] = ei[e];
}

// ---------------------------- GEMM 1 (tf32 wmma) ---------------------------
// h1[N,128] = X[N,128] @ W1[128,128]; h1 -> fp16; alpha1 from fp32 acc.
// BM=64, BN=128, BK=32. 8 warps: wm=wid>>1 (rows), wn=wid&1 (col half).
__global__ __launch_bounds__(256) void gemm1_tf32(
    const float* __restrict__ X, const float* __restrict__ W,
    const float* __restrict__ a_src, const float* __restrict__ a_dst, int N) {

    __shared__ __align__(16) char smraw[64 * 128 * 4];   // 32 KB overlay
    float (*Xs)[32]    = reinterpret_cast<float(*)[32]>(smraw);              // [64][32]
    float (*Ws)[128]   = reinterpret_cast<float(*)[128]>(smraw + 64*32*4);   // [32][128]
    float (*outb)[128] = reinterpret_cast<float(*)[128]>(smraw);             // [64][128]
    __shared__ float asb[128], adb[128];

    int t   = threadIdx.x;
    int wid = t >> 5;
    int wm  = wid >> 1;
    int wn  = wid & 1;
    int r0  = blockIdx.x * 64;

    if (t < 128) { asb[t] = a_src[t]; adb[t] = a_dst[t]; }

    wmma::fragment<wmma::accumulator, 16, 16, 8, float> acc[4];
#pragma unroll
    for (int f = 0; f < 4; f++) wmma::fill_fragment(acc[f], 0.f);

    for (int kk = 0; kk < 128; kk += 32) {
#pragma unroll
        for (int it = 0; it < 2; it++) {
            int idx = t + it * 256;
            int m = idx >> 3, j0 = (idx & 7) * 4;
            int n = r0 + m;
            float4 v = make_float4(0.f, 0.f, 0.f, 0.f);
            if (n < N) v = *(const float4*)(X + (size_t)n * 128 + kk + j0);
            *(float4*)&Xs[m][j0] = v;
        }
#pragma unroll
        for (int it = 0; it < 4; it++) {
            int idx = t + it * 256;
            int k = idx >> 5, n4 = (idx & 31) * 4;
            *(float4*)&Ws[k][n4] = *(const float4*)(W + (size_t)(kk + k) * 128 + n4);
        }
        __syncthreads();

#pragma unroll
        for (int ks = 0; ks < 4; ks++) {
            int k0 = ks * 8;
            wmma::fragment<wmma::matrix_a, 16, 16, 8, wmma::precision::tf32, wmma::row_major> a;
            wmma::load_matrix_sync(a, &Xs[wm * 16][k0], 32);
#pragma unroll
            for (int i = 0; i < a.num_elements; i++) a.x[i] = wmma::__float_to_tf32(a.x[i]);
#pragma unroll
            for (int f = 0; f < 4; f++) {
                wmma::fragment<wmma::matrix_b, 16, 16, 8, wmma::precision::tf32, wmma::row_major> b;
                wmma::load_matrix_sync(b, &Ws[k0][wn * 64 + f * 16], 128);
#pragma unroll
                for (int i = 0; i < b.num_elements; i++) b.x[i] = wmma::__float_to_tf32(b.x[i]);
                wmma::mma_sync(acc[f], a, b, acc[f]);
            }
        }
        __syncthreads();
    }

#pragma unroll
    for (int f = 0; f < 4; f++)
        wmma::store_matrix_sync(&outb[wm * 16][wn * 64 + f * 16], acc[f], 128, wmma::mem_row_major);
    __syncthreads();

    // write h1 as fp16: 64 rows * 64 half2 = 4096, 16 per thread
#pragma unroll
    for (int it = 0; it < 16; it++) {
        int idx = t + it * 256;
        int m = idx >> 6, c2 = idx & 63;
        int n = r0 + m;
        if (n < N) {
            __half2 hv = __float22half2_rn(
                make_float2(outb[m][c2 * 2], outb[m][c2 * 2 + 1]));
            ((__half2*)(g_h1h + (size_t)n * 128))[c2] = hv;
        }
    }

    // alpha1 dots from fp32 outb: thread = (row, head); rotated reads
    {
        int row = t >> 2, h = t & 3;
        int base = h * 32;
        float s = 0.f, d = 0.f;
#pragma unroll
        for (int i = 0; i < 32; i++) {
            int c = (t + i) & 31;
            float v = outb[row][base + c];
            s = fmaf(v, asb[base + c], s);
            d = fmaf(v, adb[base + c], d);
        }
        int n = r0 + row;
        if (n < N) { g_as1[n * 4 + h] = s; g_ad1[n * 4 + h] = d; }
    }
}

// ---------------------------- gather 1 -------------------------------------
// Warp per node: softmax aggregation over in-edges + self-loop; h1 rows fp16
// (8B/lane = 4 values); writes x2 = elu(num/den + b1) in FP32.
__global__ void gather1(const float* __restrict__ b1, int N) {
    int node = (blockIdx.x * blockDim.x + threadIdx.x) >> 5;
    int lane = threadIdx.x & 31;
    if (node >= N) return;
    int head = lane >> 3;

    float ad = __ldg(g_ad1 + node * 4 + head);

    float ex = expf(lrelu(__ldg(g_as1 + node * 4 + head) + ad));
    uint2 u = __ldg((const uint2*)(g_h1h + (size_t)node * 128 + lane * 4));
    float2 lo = __half22float2(*reinterpret_cast<__half2*>(&u.x));
    float2 hi = __half22float2(*reinterpret_cast<__half2*>(&u.y));
    float4 num = make_float4(lo.x * ex, lo.y * ex, hi.x * ex, hi.y * ex);
    float den = ex;

    int beg = g_off[node], end = g_off[node + 1];
#pragma unroll 4
    for (int i = beg; i < end; i++) {
        int s = __ldg(g_csr + i);
        float ex2 = expf(lrelu(__ldg(g_as1 + s * 4 + head) + ad));
        uint2 u2 = __ldg((const uint2*)(g_h1h + (size_t)s * 128 + lane * 4));
        float2 l2 = __half22float2(*reinterpret_cast<__half2*>(&u2.x));
        float2 h2 = __half22float2(*reinterpret_cast<__half2*>(&u2.y));
        num.x = fmaf(l2.x, ex2, num.x);
        num.y = fmaf(l2.y, ex2, num.y);
        num.z = fmaf(h2.x, ex2, num.z);
        num.w = fmaf(h2.y, ex2, num.w);
        den += ex2;
    }

    float inv = 1.f / (den + 1e-16f);
    int c = lane * 4;
    float4 v;
    v.x = elu(num.x * inv + b1[c + 0]);
    v.y = elu(num.y * inv + b1[c + 1]);
    v.z = elu(num.z * inv + b1[c + 2]);
    v.w = elu(num.w * inv + b1[c + 3]);
    *(float4*)(g_x2 + (size_t)node * 128 + c) = v;
}

// ---------------------------- GEMM 2 (fp32 SIMT) ---------------------------
// h2[N,64] = x2[N,128] @ W2[128,64]; h2 -> fp16; alpha2 epilogue.
// BM=64, BN=64, BK=16. 256 thr: tc=t&15 (4 cols), tr=t>>4 (4 rows).
__global__ __launch_bounds__(256) void gemm2_simt(
    const float* __restrict__ W,
    const float* __restrict__ a_src, const float* __restrict__ a_dst, int N) {

    __shared__ __align__(16) float Xs[16][64];
    __shared__ __align__(16) float Ws[16][64];

    int t  = threadIdx.x;
    int tc = t & 15, tr = t >> 4;
    int r0 = blockIdx.x * 64;

    float acc[4][4];
#pragma unroll
    for (int i = 0; i < 4; i++)
#pragma unroll
        for (int j = 0; j < 4; j++) acc[i][j] = 0.f;

    for (int kk = 0; kk < 128; kk += 16) {
        {
            int m = t >> 2, j0 = (t & 3) * 4;
            int n = r0 + m;
            float4 v = make_float4(0.f, 0.f, 0.f, 0.f);
            if (n < N) v = *(const float4*)(g_x2 + (size_t)n * 128 + kk + j0);
            Xs[j0 + 0][m] = v.x; Xs[j0 + 1][m] = v.y;
            Xs[j0 + 2][m] = v.z; Xs[j0 + 3][m] = v.w;
        }
        {
            int k = t >> 4, n4 = (t & 15) * 4;
            *(float4*)&Ws[k][n4] = *(const float4*)(W + (size_t)(kk + k) * 64 + n4);
        }
        __syncthreads();

#pragma unroll
        for (int k = 0; k < 16; k++) {
            float4 a4 = *(float4*)&Xs[k][tr * 4];
            float4 b4 = *(float4*)&Ws[k][tc * 4];
            float a[4] = {a4.x, a4.y, a4.z, a4.w};
            float b[4] = {b4.x, b4.y, b4.z, b4.w};
#pragma unroll
            for (int i = 0; i < 4; i++)
#pragma unroll
                for (int j = 0; j < 4; j++) acc[i][j] = fmaf(a[i], b[j], acc[i][j]);
        }
        __syncthreads();
    }

    float av[4], dv[4];
#pragma unroll
    for (int j = 0; j < 4; j++) { av[j] = a_src[tc * 4 + j]; dv[j] = a_dst[tc * 4 + j]; }

#pragma unroll
    for (int i = 0; i < 4; i++) {
        int n = r0 + tr * 4 + i;
        if (n >= N) break;
        // h2 as fp16: 4 cols -> 2 half2 (8B, aligned: tc*4 halves = tc*8 bytes)
        __half2 p0 = __float22half2_rn(make_float2(acc[i][0], acc[i][1]));
        __half2 p1 = __float22half2_rn(make_float2(acc[i][2], acc[i][3]));
        __half2* dst = (__half2*)(g_h2h + (size_t)n * 64 + tc * 4);
        dst[0] = p0; dst[1] = p1;
        float s = 0.f, d = 0.f;
#pragma unroll
        for (int j = 0; j < 4; j++) { s = fmaf(acc[i][j], av[j], s); d = fmaf(acc[i][j], dv[j], d); }
        s += __shfl_xor_sync(0xFFFFFFFFu, s, 1); d += __shfl_xor_sync(0xFFFFFFFFu, d, 1);
        s += __shfl_xor_sync(0xFFFFFFFFu, s, 2); d += __shfl_xor_sync(0xFFFFFFFFu, d, 2);
        s += __shfl_xor_sync(0xFFFFFFFFu, s, 4); d += __shfl_xor_sync(0xFFFFFFFFu, d, 4);
        s += __shfl_xor_sync(0xFFFFFFFFu, s, 8); d += __shfl_xor_sync(0xFFFFFFFFu, d, 8);
        if (tc == 0) { g_as2[n] = s; g_ad2[n] = d; }
    }
}

// ---------------------------- gather 2 -------------------------------------
// Warp per node; lane covers 2 channels (one half2). out = num/den + b2.
__global__ void gather2(float* __restrict__ out, const float* __restrict__ b2, int N) {
    int node = (blockIdx.x * blockDim.x + threadIdx.x) >> 5;
    int lane = threadIdx.x & 31;
    if (node >= N) return;

    float ad = __ldg(g_ad2 + node);

    float ex = expf(lrelu(__ldg(g_as2 + node) + ad));
    float2 hv = __half22float2(
        *(const __half2*)(g_h2h + (size_t)node * 64 + lane * 2));
    float2 num = make_float2(hv.x * ex, hv.y * ex);
    float den = ex;

    int beg = g_off[node], end = g_off[node + 1];
#pragma unroll 4
    for (int i = beg; i < end; i++) {
        int s = __ldg(g_csr + i);
        float ex2 = expf(lrelu(__ldg(g_as2 + s) + ad));
        float2 h = __half22float2(
            *(const __half2*)(g_h2h + (size_t)s * 64 + lane * 2));
        num.x = fmaf(h.x, ex2, num.x);
        num.y = fmaf(h.y, ex2, num.y);
        den += ex2;
    }

    float inv = 1.f / (den + 1e-16f);
    int c = lane * 2;
    float2 v;
    v.x = num.x * inv + b2[c + 0];
    v.y = num.y * inv + b2[c + 1];
    *(float2*)(out + (size_t)node * 64 + c) = v;
}

// ---------------------------------------------------------------------------
extern "C" void kernel_launch(void* const* d_in, const int* in_sizes, int n_in,
                              void* d_out, int out_size) {
    const float* x      = (const float*)d_in[0];
    const int*   ei     = (const int*)d_in[1];     // int32 (JAX x64 off)
    const float* W1     = (const float*)d_in[2];
    const float* a_src1 = (const float*)d_in[3];
    const float* a_dst1 = (const float*)d_in[4];
    const float* b1     = (const float*)d_in[5];
    const float* W2     = (const float*)d_in[6];
    const float* a_src2 = (const float*)d_in[7];
    const float* a_dst2 = (const float*)d_in[8];
    const float* b2     = (const float*)d_in[9];
    float*       out    = (float*)d_out;

    int N = in_sizes[0] / 128;
    int E = in_sizes[1] / 2;
    const int TB = 256;
    int NB = (N + 1023) / 1024;

    // ---- CSR build ----
    csr_zero<<<(N + TB - 1) / TB, TB>>>(N);
    csr_hist<<<(E + TB - 1) / TB, TB>>>(ei, E);
    scan1<<<NB, 1024>>>(N);
    scan2<<<1, 128>>>(NB);
    scan3<<<(N + TB - 1) / TB, TB>>>(N);
    csr_scatter<<<(E + TB - 1) / TB, TB>>>(ei, E);

    // ---- layer 1 ----
    gemm1_tf32<<<(N + 63) / 64, 256>>>(x, W1, a_src1, a_dst1, N);
    gather1<<<(N + 7) / 8, TB>>>(b1, N);

    // ---- layer 2 ----
    gemm2_simt<<<(N + 63) / 64, 256>>>(W2, a_src2, a_dst2, N);
    gather2<<<(N + 7) / 8, TB>>>(out, b2, N);
}

// round 16
// speedup vs baseline: 1.1361x; 1.1361x over previous
#include <cuda_runtime.h>
#include <mma.h>

using namespace nvcuda;

// ---------------------------------------------------------------------------
// GAT (2-layer, PyG-style) on GB300 — R15: R11 config (best measured) +
// __expf fast-exp in all edge loops.
//
// Component choices, all measurement-backed:
//   gemm1 tf32 wmma   (R11/R12: faster than fp32 SIMT at N=128)
//   gemm2 fp32 SIMT   (R13: tf32 wmma SLOWER at N=64 — reverted)
//   features fp32     (R12 bf16: rel_err blowup; R14 fp16: slower — gathers
//                      are issue/latency-bound, not BW-bound)
//   __expf            (expf is ~15-20 instrs; __expf is 2; rel err 5e-7)
//
// Pipeline:
//   CSR build (6 small kernels) -> gemm1_tf32(+alpha1) -> gather1 ->
//   gemm2_simt(+alpha2) -> gather2 (writes final out)
//
// Softmax max-shift dropped (|e| small, exp bounded — exact same math).
// edge_index is int32 (JAX x64 disabled).
// ---------------------------------------------------------------------------

#define NEG_SLOPE 0.2f
#define MAXN 100000
#define MAXE 1600000

__device__ __align__(16) float g_h1 [MAXN * 128];
__device__ __align__(16) float g_x2 [MAXN * 128];
__device__ __align__(16) float g_as1[MAXN * 4];
__device__ __align__(16) float g_ad1[MAXN * 4];
__device__ __align__(16) float g_h2 [MAXN * 64];
__device__ __align__(16) float g_as2[MAXN];
__device__ __align__(16) float g_ad2[MAXN];

__device__ int g_deg [MAXN];
__device__ int g_fill[MAXN];
__device__ int g_off [MAXN + 1];
__device__ int g_aux [128];
__device__ int g_csr [MAXE];

__device__ __forceinline__ float lrelu(float e) { return fmaxf(e, NEG_SLOPE * e); }
__device__ __forceinline__ float fexp(float x)  { return __expf(x); }   // 2 instrs
__device__ __forceinline__ float elu(float v)   { return (v > 0.f) ? v : (fexp(v) - 1.f); }

// ---------------------------- CSR build ------------------------------------
__global__ void csr_zero(int N) {
    int i = blockIdx.x * blockDim.x + threadIdx.x;
    if (i < N) { g_deg[i] = 0; g_fill[i] = 0; }
}

__global__ void csr_hist(const int* __restrict__ ei, int E) {
    int e = blockIdx.x * blockDim.x + threadIdx.x;
    if (e < E) atomicAdd(&g_deg[ei[E + e]], 1);
}

__global__ __launch_bounds__(1024) void scan1(int N) {
    __shared__ int sm[1024];
    int t = threadIdx.x;
    int i = blockIdx.x * 1024 + t;
    sm[t] = (i < N) ? g_deg[i] : 0;
    __syncthreads();
    for (int ofs = 1; ofs < 1024; ofs <<= 1) {
        int add = (t >= ofs) ? sm[t - ofs] : 0;
        __syncthreads();
        sm[t] += add;
        __syncthreads();
    }
    if (i < N) g_off[i + 1] = sm[t];
    if (t == 1023) g_aux[blockIdx.x] = sm[1023];
    if (i == 0) g_off[0] = 0;
}

__global__ void scan2(int NB) {
    __shared__ int sm[128];
    int t = threadIdx.x;
    sm[t] = (t < NB) ? g_aux[t] : 0;
    __syncthreads();
    for (int ofs = 1; ofs < 128; ofs <<= 1) {
        int add = (t >= ofs) ? sm[t - ofs] : 0;
        __syncthreads();
        sm[t] += add;
        __syncthreads();
    }
    if (t < NB) g_aux[t] = (t == 0) ? 0 : sm[t - 1];
}

__global__ void scan3(int N) {
    int i = blockIdx.x * blockDim.x + threadIdx.x;
    if (i < N) g_off[i + 1] += g_aux[i >> 10];
}

__global__ void csr_scatter(const int* __restrict__ ei, int E) {
    int e = blockIdx.x * blockDim.x + threadIdx.x;
    if (e >= E) return;
    int d = ei[E + e];
    int pos = g_off[d] + atomicAdd(&g_fill[d], 1);
    g_csr[pos] = ei[e];
}

// ---------------------------- GEMM 1 (tf32 wmma) ---------------------------
// h1[N,128] = X[N,128] @ W1[128,128] + alpha1 epilogue.
// BM=64, BN=128, BK=32. 8 warps: wm=wid>>1 (rows), wn=wid&1 (col half).
__global__ __launch_bounds__(256) void gemm1_tf32(
    const float* __restrict__ X, const float* __restrict__ W,
    const float* __restrict__ a_src, const float* __restrict__ a_dst, int N) {

    __shared__ __align__(16) char smraw[64 * 128 * 4];   // 32 KB overlay
    float (*Xs)[32]    = reinterpret_cast<float(*)[32]>(smraw);              // [64][32]
    float (*Ws)[128]   = reinterpret_cast<float(*)[128]>(smraw + 64*32*4);   // [32][128]
    float (*outb)[128] = reinterpret_cast<float(*)[128]>(smraw);             // [64][128]
    __shared__ float asb[128], adb[128];

    int t   = threadIdx.x;
    int wid = t >> 5;
    int wm  = wid >> 1;
    int wn  = wid & 1;
    int r0  = blockIdx.x * 64;

    if (t < 128) { asb[t] = a_src[t]; adb[t] = a_dst[t]; }

    wmma::fragment<wmma::accumulator, 16, 16, 8, float> acc[4];
#pragma unroll
    for (int f = 0; f < 4; f++) wmma::fill_fragment(acc[f], 0.f);

    for (int kk = 0; kk < 128; kk += 32) {
#pragma unroll
        for (int it = 0; it < 2; it++) {
            int idx = t + it * 256;
            int m = idx >> 3, j0 = (idx & 7) * 4;
            int n = r0 + m;
            float4 v = make_float4(0.f, 0.f, 0.f, 0.f);
            if (n < N) v = *(const float4*)(X + (size_t)n * 128 + kk + j0);
            *(float4*)&Xs[m][j0] = v;
        }
#pragma unroll
        for (int it = 0; it < 4; it++) {
            int idx = t + it * 256;
            int k = idx >> 5, n4 = (idx & 31) * 4;
            *(float4*)&Ws[k][n4] = *(const float4*)(W + (size_t)(kk + k) * 128 + n4);
        }
        __syncthreads();

#pragma unroll
        for (int ks = 0; ks < 4; ks++) {
            int k0 = ks * 8;
            wmma::fragment<wmma::matrix_a, 16, 16, 8, wmma::precision::tf32, wmma::row_major> a;
            wmma::load_matrix_sync(a, &Xs[wm * 16][k0], 32);
#pragma unroll
            for (int i = 0; i < a.num_elements; i++) a.x[i] = wmma::__float_to_tf32(a.x[i]);
#pragma unroll
            for (int f = 0; f < 4; f++) {
                wmma::fragment<wmma::matrix_b, 16, 16, 8, wmma::precision::tf32, wmma::row_major> b;
                wmma::load_matrix_sync(b, &Ws[k0][wn * 64 + f * 16], 128);
#pragma unroll
                for (int i = 0; i < b.num_elements; i++) b.x[i] = wmma::__float_to_tf32(b.x[i]);
                wmma::mma_sync(acc[f], a, b, acc[f]);
            }
        }
        __syncthreads();
    }

#pragma unroll
    for (int f = 0; f < 4; f++)
        wmma::store_matrix_sync(&outb[wm * 16][wn * 64 + f * 16], acc[f], 128, wmma::mem_row_major);
    __syncthreads();

    // write h1 (coalesced): 2048 float4, 8 per thread
#pragma unroll
    for (int it = 0; it < 8; it++) {
        int idx = t + it * 256;
        int m = idx >> 5, c4 = (idx & 31) * 4;
        int n = r0 + m;
        if (n < N) *(float4*)(g_h1 + (size_t)n * 128 + c4) = *(float4*)&outb[m][c4];
    }

    // alpha1 dots: thread = (row, head); rotated reads avoid bank conflicts
    {
        int row = t >> 2, h = t & 3;
        int base = h * 32;
        float s = 0.f, d = 0.f;
#pragma unroll
        for (int i = 0; i < 32; i++) {
            int c = (t + i) & 31;
            float v = outb[row][base + c];
            s = fmaf(v, asb[base + c], s);
            d = fmaf(v, adb[base + c], d);
        }
        int n = r0 + row;
        if (n < N) { g_as1[n * 4 + h] = s; g_ad1[n * 4 + h] = d; }
    }
}

// ---------------------------- gather 1 -------------------------------------
// Warp per node: softmax-weighted aggregation over in-edges + self-loop,
// all in registers; writes x2 = elu(num/den + b1).
__global__ void gather1(const float* __restrict__ b1, int N) {
    int node = (blockIdx.x * blockDim.x + threadIdx.x) >> 5;
    int lane = threadIdx.x & 31;
    if (node >= N) return;
    int head = lane >> 3;

    float ad = __ldg(g_ad1 + node * 4 + head);

    float ex = fexp(lrelu(__ldg(g_as1 + node * 4 + head) + ad));
    float4 hv = *(const float4*)(g_h1 + (size_t)node * 128 + lane * 4);
    float4 num = make_float4(hv.x * ex, hv.y * ex, hv.z * ex, hv.w * ex);
    float den = ex;

    int beg = g_off[node], end = g_off[node + 1];
#pragma unroll 4
    for (int i = beg; i < end; i++) {
        int s = __ldg(g_csr + i);
        float ex2 = fexp(lrelu(__ldg(g_as1 + s * 4 + head) + ad));
        float4 h = *(const float4*)(g_h1 + (size_t)s * 128 + lane * 4);
        num.x = fmaf(h.x, ex2, num.x);
        num.y = fmaf(h.y, ex2, num.y);
        num.z = fmaf(h.z, ex2, num.z);
        num.w = fmaf(h.w, ex2, num.w);
        den += ex2;
    }

    float inv = 1.f / (den + 1e-16f);
    int c = lane * 4;
    float4 v;
    v.x = elu(num.x * inv + b1[c + 0]);
    v.y = elu(num.y * inv + b1[c + 1]);
    v.z = elu(num.z * inv + b1[c + 2]);
    v.w = elu(num.w * inv + b1[c + 3]);
    *(float4*)(g_x2 + (size_t)node * 128 + c) = v;
}

// ---------------------------- GEMM 2 (fp32 SIMT) ---------------------------
// h2[N,64] = x2[N,128] @ W2[128,64] + alpha2 epilogue.
// BM=64, BN=64, BK=16. 256 thr: tc=t&15 (4 cols), tr=t>>4 (4 rows).
__global__ __launch_bounds__(256) void gemm2_simt(
    const float* __restrict__ W,
    const float* __restrict__ a_src, const float* __restrict__ a_dst, int N) {

    __shared__ __align__(16) float Xs[16][64];
    __shared__ __align__(16) float Ws[16][64];

    int t  = threadIdx.x;
    int tc = t & 15, tr = t >> 4;
    int r0 = blockIdx.x * 64;

    float acc[4][4];
#pragma unroll
    for (int i = 0; i < 4; i++)
#pragma unroll
        for (int j = 0; j < 4; j++) acc[i][j] = 0.f;

    for (int kk = 0; kk < 128; kk += 16) {
        {
            int m = t >> 2, j0 = (t & 3) * 4;
            int n = r0 + m;
            float4 v = make_float4(0.f, 0.f, 0.f, 0.f);
            if (n < N) v = *(const float4*)(g_x2 + (size_t)n * 128 + kk + j0);
            Xs[j0 + 0][m] = v.x; Xs[j0 + 1][m] = v.y;
            Xs[j0 + 2][m] = v.z; Xs[j0 + 3][m] = v.w;
        }
        {
            int k = t >> 4, n4 = (t & 15) * 4;
            *(float4*)&Ws[k][n4] = *(const float4*)(W + (size_t)(kk + k) * 64 + n4);
        }
        __syncthreads();

#pragma unroll
        for (int k = 0; k < 16; k++) {
            float4 a4 = *(float4*)&Xs[k][tr * 4];
            float4 b4 = *(float4*)&Ws[k][tc * 4];
            float a[4] = {a4.x, a4.y, a4.z, a4.w};
            float b[4] = {b4.x, b4.y, b4.z, b4.w};
#pragma unroll
            for (int i = 0; i < 4; i++)
#pragma unroll
                for (int j = 0; j < 4; j++) acc[i][j] = fmaf(a[i], b[j], acc[i][j]);
        }
        __syncthreads();
    }

    float av[4], dv[4];
#pragma unroll
    for (int j = 0; j < 4; j++) { av[j] = a_src[tc * 4 + j]; dv[j] = a_dst[tc * 4 + j]; }

#pragma unroll
    for (int i = 0; i < 4; i++) {
        int n = r0 + tr * 4 + i;
        if (n >= N) break;
        *(float4*)(g_h2 + (size_t)n * 64 + tc * 4) =
            make_float4(acc[i][0], acc[i][1], acc[i][2], acc[i][3]);
        float s = 0.f, d = 0.f;
#pragma unroll
        for (int j = 0; j < 4; j++) { s = fmaf(acc[i][j], av[j], s); d = fmaf(acc[i][j], dv[j], d); }
        s += __shfl_xor_sync(0xFFFFFFFFu, s, 1); d += __shfl_xor_sync(0xFFFFFFFFu, d, 1);
        s += __shfl_xor_sync(0xFFFFFFFFu, s, 2); d += __shfl_xor_sync(0xFFFFFFFFu, d, 2);
        s += __shfl_xor_sync(0xFFFFFFFFu, s, 4); d += __shfl_xor_sync(0xFFFFFFFFu, d, 4);
        s += __shfl_xor_sync(0xFFFFFFFFu, s, 8); d += __shfl_xor_sync(0xFFFFFFFFu, d, 8);
        if (tc == 0) { g_as2[n] = s; g_ad2[n] = d; }
    }
}

// ---------------------------- gather 2 -------------------------------------
// Warp per node; lane covers 2 channels. Writes final out = num/den + b2.
__global__ void gather2(float* __restrict__ out, const float* __restrict__ b2, int N) {
    int node = (blockIdx.x * blockDim.x + threadIdx.x) >> 5;
    int lane = threadIdx.x & 31;
    if (node >= N) return;

    float ad = __ldg(g_ad2 + node);

    float ex = fexp(lrelu(__ldg(g_as2 + node) + ad));
    float2 hv = *(const float2*)(g_h2 + (size_t)node * 64 + lane * 2);
    float2 num = make_float2(hv.x * ex, hv.y * ex);
    float den = ex;

    int beg = g_off[node], end = g_off[node + 1];
#pragma unroll 4
    for (int i = beg; i < end; i++) {
        int s = __ldg(g_csr + i);
        float ex2 = fexp(lrelu(__ldg(g_as2 + s) + ad));
        float2 h = *(const float2*)(g_h2 + (size_t)s * 64 + lane * 2);
        num.x = fmaf(h.x, ex2, num.x);
        num.y = fmaf(h.y, ex2, num.y);
        den += ex2;
    }

    float inv = 1.f / (den + 1e-16f);
    int c = lane * 2;
    float2 v;
    v.x = num.x * inv + b2[c + 0];
    v.y = num.y * inv + b2[c + 1];
    *(float2*)(out + (size_t)node * 64 + c) = v;
}

// ---------------------------------------------------------------------------
extern "C" void kernel_launch(void* const* d_in, const int* in_sizes, int n_in,
                              void* d_out, int out_size) {
    const float* x      = (const float*)d_in[0];
    const int*   ei     = (const int*)d_in[1];     // int32 (JAX x64 off)
    const float* W1     = (const float*)d_in[2];
    const float* a_src1 = (const float*)d_in[3];
    const float* a_dst1 = (const float*)d_in[4];
    const float* b1     = (const float*)d_in[5];
    const float* W2     = (const float*)d_in[6];
    const float* a_src2 = (const float*)d_in[7];
    const float* a_dst2 = (const float*)d_in[8];
    const float* b2     = (const float*)d_in[9];
    float*       out    = (float*)d_out;

    int N = in_sizes[0] / 128;
    int E = in_sizes[1] / 2;
    const int TB = 256;
    int NB = (N + 1023) / 1024;

    // ---- CSR build ----
    csr_zero<<<(N + TB - 1) / TB, TB>>>(N);
    csr_hist<<<(E + TB - 1) / TB, TB>>>(ei, E);
    scan1<<<NB, 1024>>>(N);
    scan2<<<1, 128>>>(NB);
    scan3<<<(N + TB - 1) / TB, TB>>>(N);
    csr_scatter<<<(E + TB - 1) / TB, TB>>>(ei, E);

    // ---- layer 1 ----
    gemm1_tf32<<<(N + 63) / 64, 256>>>(x, W1, a_src1, a_dst1, N);
    gather1<<<(N + 7) / 8, TB>>>(b1, N);

    // ---- layer 2 ----
    gemm2_simt<<<(N + 63) / 64, 256>>>(W2, a_src2, a_dst2, N);
    gather2<<<(N + 7) / 8, TB>>>(out, b2, N);
}